// round 6
// baseline (speedup 1.0000x reference)
#include <cuda_runtime.h>
#include <cuda_bf16.h>
#include <cstdint>

// Tree-RNN, bf16x3-split GEMMs on mma.sync tensor cores.
// 4-stage cp.async ring, prefetch distance 3 (wait_group 2), ONE
// __syncthreads per k-tile, term-outer MMA order for 8-way acc ILP.

#define BM 128
#define BN 64
#define BK 32
#define A_T (BM * 128)              // 16384 B (row = hi 64B | lo 64B)
#define B_T (BN * 128)              // 8192 B
#define STAGE_B (A_T + B_T)         // 24576
#define NSTAGE 4
#define SMEM_TOTAL (NSTAGE * STAGE_B)   // 98304

// ---------------- device scratch (no allocation allowed) ----------------
__device__ __nv_bfloat16 g_leaf_hi[8192ull * 4096];
__device__ __nv_bfloat16 g_leaf_lo[8192ull * 4096];
__device__ __nv_bfloat16 g_We_hi[512 * 4096];
__device__ __nv_bfloat16 g_We_lo[512 * 4096];
__device__ __nv_bfloat16 g_Wc_hi[512 * 1024];
__device__ __nv_bfloat16 g_Wc_lo[512 * 1024];
__device__ __nv_bfloat16 g_hA[8192 * 512], g_lA[8192 * 512];
__device__ __nv_bfloat16 g_hB[4096 * 512], g_lB[4096 * 512];

// ---------------- PTX helpers ----------------
__device__ __forceinline__ void mma_bf16(float c[4], const uint32_t a[4],
                                         const uint32_t b0, const uint32_t b1) {
    asm volatile(
        "mma.sync.aligned.m16n8k16.row.col.f32.bf16.bf16.f32 "
        "{%0,%1,%2,%3}, {%4,%5,%6,%7}, {%8,%9}, {%0,%1,%2,%3};\n"
        : "+f"(c[0]), "+f"(c[1]), "+f"(c[2]), "+f"(c[3])
        : "r"(a[0]), "r"(a[1]), "r"(a[2]), "r"(a[3]), "r"(b0), "r"(b1));
}
__device__ __forceinline__ void cp16(uint32_t dst, const void* src, bool p) {
    asm volatile("cp.async.cg.shared.global [%0], [%1], 16, %2;"
                 :: "r"(dst), "l"(src), "r"(p ? 16 : 0));
}
__device__ __forceinline__ void cp_commit() {
    asm volatile("cp.async.commit_group;");
}
template <int N> __device__ __forceinline__ void cp_wait() {
    asm volatile("cp.async.wait_group %0;" :: "n"(N));
}
__device__ __forceinline__ void ldsm4(uint32_t r[4], uint32_t a) {
    asm volatile("ldmatrix.sync.aligned.m8n8.x4.shared.b16 {%0,%1,%2,%3}, [%4];"
                 : "=r"(r[0]), "=r"(r[1]), "=r"(r[2]), "=r"(r[3]) : "r"(a));
}
__device__ __forceinline__ uint32_t pack_bf2(__nv_bfloat16 a, __nv_bfloat16 b) {
    __nv_bfloat162 t{a, b};
    return *reinterpret_cast<uint32_t*>(&t);
}

// ---------------- fp32 -> bf16 hi/lo split (streaming) ----------------
__global__ void split_kernel(const float4* __restrict__ src,
                             uint2* __restrict__ hi, uint2* __restrict__ lo,
                             int n4)
{
    int i = blockIdx.x * blockDim.x + threadIdx.x;
    const int stride = gridDim.x * blockDim.x;
    for (; i < n4; i += stride) {
        float4 v = src[i];
        __nv_bfloat16 h0 = __float2bfloat16(v.x), h1 = __float2bfloat16(v.y);
        __nv_bfloat16 h2 = __float2bfloat16(v.z), h3 = __float2bfloat16(v.w);
        uint2 H, L;
        H.x = pack_bf2(h0, h1);
        H.y = pack_bf2(h2, h3);
        L.x = pack_bf2(__float2bfloat16(v.x - __bfloat162float(h0)),
                       __float2bfloat16(v.y - __bfloat162float(h1)));
        L.y = pack_bf2(__float2bfloat16(v.z - __bfloat162float(h2)),
                       __float2bfloat16(v.w - __bfloat162float(h3)));
        hi[i] = H;
        lo[i] = L;
    }
}

// ---------------------------------------------------------------------------
// C = relu(A @ W^T + bias): A [M,K] hi/lo bf16, W [N,K] hi/lo bf16,
// C emitted as hi/lo bf16. K%32==0, N%64==0, M bounds-checked.
// 256 threads = 8 warps (4 M x 2 N of 32x32 warp tiles).
// ---------------------------------------------------------------------------
__global__ __launch_bounds__(256, 2)
void gemm_bf16x3(const __nv_bfloat16* __restrict__ Ahi,
                 const __nv_bfloat16* __restrict__ Alo,
                 const __nv_bfloat16* __restrict__ Whi,
                 const __nv_bfloat16* __restrict__ Wlo,
                 const float* __restrict__ bias,
                 __nv_bfloat16* __restrict__ Chi,
                 __nv_bfloat16* __restrict__ Clo,
                 int M, int N, int K)
{
    extern __shared__ __align__(1024) char smem[];
    const uint32_t sbase = (uint32_t)__cvta_generic_to_shared(smem);

    const int tid  = threadIdx.x;
    const int lane = tid & 31;
    const int wid  = tid >> 5;
    const int wm   = (wid & 3) * 32;
    const int wn   = (wid >> 2) * 32;
    const int bm   = blockIdx.y * BM;
    const int bn   = blockIdx.x * BN;

    // ldmatrix lane mapping
    const int lr8   = lane & 7;
    const int g     = lane >> 3;
    const int mrow  = (g & 1) * 8;
    const int kcolB = (g >> 1) * 16;

    // Per-thread swizzled row bases for frag loads.
    uint32_t aRow[2], aXm[2], bRow[2], bXm[2];
    #pragma unroll
    for (int mi = 0; mi < 2; mi++) {
        const uint32_t rB = (uint32_t)(wm + mi * 16 + mrow + lr8) * 128;
        aRow[mi] = rB;
        aXm[mi]  = (rB >> 3) & 0x70;
    }
    #pragma unroll
    for (int p = 0; p < 2; p++) {
        const uint32_t rB = (uint32_t)(wn + p * 16 + mrow + lr8) * 128;
        bRow[p] = A_T + rB;
        bXm[p]  = (rB >> 3) & 0x70;
    }

    float acc[2][4][4];
    #pragma unroll
    for (int i = 0; i < 2; i++)
        #pragma unroll
        for (int j = 0; j < 4; j++)
            #pragma unroll
            for (int v = 0; v < 4; v++) acc[i][j][v] = 0.f;

    const int nT = K / BK;

    auto stage = [&](int lt) {
        const uint32_t sb = sbase + (lt & (NSTAGE - 1)) * STAGE_B;
        const int k0 = lt * BK;
        #pragma unroll
        for (int i = 0; i < 4; i++) {
            const int lin = tid + i * 256;
            const int r = lin >> 3;
            const int c = lin & 7;
            const uint32_t off = (uint32_t)r * 128 + (uint32_t)c * 16;
            const uint32_t sw = off ^ ((off >> 3) & 0x70);
            const bool pa = (bm + r) < M;
            const __nv_bfloat16* src = (c < 4) ? Ahi : Alo;
            cp16(sb + sw, src + (size_t)(bm + r) * K + k0 + (c & 3) * 8, pa);
        }
        #pragma unroll
        for (int i = 0; i < 2; i++) {
            const int lin = tid + i * 256;
            const int r = lin >> 3;
            const int c = lin & 7;
            const uint32_t off = (uint32_t)r * 128 + (uint32_t)c * 16;
            const uint32_t sw = off ^ ((off >> 3) & 0x70);
            const __nv_bfloat16* src = (c < 4) ? Whi : Wlo;
            cp16(sb + A_T + sw, src + (size_t)(bn + r) * K + k0 + (c & 3) * 8, true);
        }
        cp_commit();
    };

    // prologue: prefetch 3 tiles (ring holds 4)
    stage(0);
    stage(1);
    stage(2);

    for (int kt = 0; kt < nT; kt++) {
        // tile kt must be complete; newest (up to) 2 groups may stay pending
        if (kt + 2 <= nT - 1)      cp_wait<2>();
        else if (kt + 1 <= nT - 1) cp_wait<1>();
        else                       cp_wait<0>();
        __syncthreads();                  // readers of slot (kt+3)&3 done
        if (kt + 3 < nT) stage(kt + 3);   // keep distance-3 prefetch

        const uint32_t s0 = sbase + (kt & (NSTAGE - 1)) * STAGE_B;

        #pragma unroll
        for (int ks = 0; ks < BK; ks += 16) {
            const uint32_t colH = (uint32_t)(ks * 2) + kcolB;       // hi region
            const uint32_t colL = 64u + (uint32_t)(ks * 2) + kcolB; // lo region
            uint32_t ah[2][4], al[2][4], bh[2][4], bl[2][4];
            #pragma unroll
            for (int mi = 0; mi < 2; mi++) {
                ldsm4(ah[mi], s0 + aRow[mi] + (colH ^ aXm[mi]));
                ldsm4(al[mi], s0 + aRow[mi] + (colL ^ aXm[mi]));
            }
            #pragma unroll
            for (int p = 0; p < 2; p++) {
                ldsm4(bh[p], s0 + bRow[p] + (colH ^ bXm[p]));
                ldsm4(bl[p], s0 + bRow[p] + (colL ^ bXm[p]));
            }
            // term-outer order: consecutive MMAs hit 8 distinct accumulators
            #pragma unroll
            for (int mi = 0; mi < 2; mi++)
                #pragma unroll
                for (int ni = 0; ni < 4; ni++) {
                    const int p = ni >> 1, q = ni & 1;
                    mma_bf16(acc[mi][ni], ah[mi], bh[p][q], bh[p][q + 2]);
                }
            #pragma unroll
            for (int mi = 0; mi < 2; mi++)
                #pragma unroll
                for (int ni = 0; ni < 4; ni++) {
                    const int p = ni >> 1, q = ni & 1;
                    mma_bf16(acc[mi][ni], ah[mi], bl[p][q], bl[p][q + 2]);
                }
            #pragma unroll
            for (int mi = 0; mi < 2; mi++)
                #pragma unroll
                for (int ni = 0; ni < 4; ni++) {
                    const int p = ni >> 1, q = ni & 1;
                    mma_bf16(acc[mi][ni], al[mi], bh[p][q], bh[p][q + 2]);
                }
        }
    }

    // ---- epilogue: bias + relu, split into hi/lo bf16 ----
    const int lq = (lane & 3) * 2;
    const int lr = lane >> 2;
    #pragma unroll
    for (int mi = 0; mi < 2; mi++) {
        #pragma unroll
        for (int ni = 0; ni < 4; ni++) {
            const int m0 = bm + wm + mi * 16 + lr;
            const int n  = bn + wn + ni * 8 + lq;
            const float bv0 = __ldg(bias + n), bv1 = __ldg(bias + n + 1);
            #pragma unroll
            for (int h = 0; h < 2; h++) {
                const int m = m0 + h * 8;
                if (m < M) {
                    float x0 = fmaxf(acc[mi][ni][2 * h]     + bv0, 0.f);
                    float x1 = fmaxf(acc[mi][ni][2 * h + 1] + bv1, 0.f);
                    __nv_bfloat16 h0 = __float2bfloat16(x0);
                    __nv_bfloat16 h1 = __float2bfloat16(x1);
                    __nv_bfloat16 l0 = __float2bfloat16(x0 - __bfloat162float(h0));
                    __nv_bfloat16 l1 = __float2bfloat16(x1 - __bfloat162float(h1));
                    *reinterpret_cast<uint32_t*>(Chi + (size_t)m * N + n) = pack_bf2(h0, h1);
                    *reinterpret_cast<uint32_t*>(Clo + (size_t)m * N + n) = pack_bf2(l0, l1);
                }
            }
        }
    }
}

// Root projection: out[c] = sum_k (hi[k]+lo[k]) * Wp[c*512+k] + bp[c]
__global__ void proj_kernel(const __nv_bfloat16* __restrict__ hhi,
                            const __nv_bfloat16* __restrict__ hlo,
                            const float* __restrict__ Wp,
                            const float* __restrict__ bp,
                            float* __restrict__ out)
{
    const int w    = threadIdx.x >> 5;
    const int lane = threadIdx.x & 31;
    float s = 0.f;
    for (int k = lane; k < 512; k += 32) {
        const float hv = __bfloat162float(hhi[k]) + __bfloat162float(hlo[k]);
        s = fmaf(hv, Wp[w * 512 + k], s);
    }
    #pragma unroll
    for (int o = 16; o > 0; o >>= 1)
        s += __shfl_xor_sync(0xffffffffu, s, o);
    if (lane == 0) out[w] = s + bp[w];
}

extern "C" void kernel_launch(void* const* d_in, const int* in_sizes, int n_in,
                              void* d_out, int out_size)
{
    const float* leaf  = (const float*)d_in[0];   // [8192, 4096]
    const float* Wemb  = (const float*)d_in[1];   // [512, 4096]
    const float* bemb  = (const float*)d_in[2];   // [512]
    const float* Wcomb = (const float*)d_in[3];   // [512, 1024]
    const float* bcomb = (const float*)d_in[4];   // [512]
    const float* Wproj = (const float*)d_in[5];   // [2, 512]
    const float* bproj = (const float*)d_in[6];   // [2]
    float* out = (float*)d_out;

    __nv_bfloat16 *leaf_hi, *leaf_lo, *We_hi, *We_lo, *Wc_hi, *Wc_lo;
    __nv_bfloat16 *hA, *lA, *hB, *lB;
    cudaGetSymbolAddress((void**)&leaf_hi, g_leaf_hi);
    cudaGetSymbolAddress((void**)&leaf_lo, g_leaf_lo);
    cudaGetSymbolAddress((void**)&We_hi, g_We_hi);
    cudaGetSymbolAddress((void**)&We_lo, g_We_lo);
    cudaGetSymbolAddress((void**)&Wc_hi, g_Wc_hi);
    cudaGetSymbolAddress((void**)&Wc_lo, g_Wc_lo);
    cudaGetSymbolAddress((void**)&hA, g_hA);
    cudaGetSymbolAddress((void**)&lA, g_lA);
    cudaGetSymbolAddress((void**)&hB, g_hB);
    cudaGetSymbolAddress((void**)&lB, g_lB);

    cudaFuncSetAttribute(gemm_bf16x3,
                         cudaFuncAttributeMaxDynamicSharedMemorySize, SMEM_TOTAL);

    // ---- pre-split fp32 inputs into bf16 hi/lo ----
    split_kernel<<<4096, 256>>>((const float4*)leaf,
                                (uint2*)leaf_hi, (uint2*)leaf_lo, 8192 * 4096 / 4);
    split_kernel<<<1024, 256>>>((const float4*)Wemb,
                                (uint2*)We_hi, (uint2*)We_lo, 512 * 4096 / 4);
    split_kernel<<<512, 256>>>((const float4*)Wcomb,
                               (uint2*)Wc_hi, (uint2*)Wc_lo, 512 * 1024 / 4);

    // ---- leaf embedding: [8192,4096] @ [512,4096]^T -> hA/lA ----
    {
        dim3 grid(512 / BN, 8192 / BM);
        gemm_bf16x3<<<grid, 256, SMEM_TOTAL>>>(leaf_hi, leaf_lo, We_hi, We_lo,
                                               bemb, hA, lA, 8192, 512, 4096);
    }

    // ---- 13 combine levels: [rows,512] viewed as [rows/2,1024] ----
    __nv_bfloat16 *cur_h = hA, *cur_l = lA, *nxt_h = hB, *nxt_l = lB;
    int rows = 8192;
    while (rows > 1) {
        const int m = rows / 2;
        dim3 grid(512 / BN, (m + BM - 1) / BM);
        gemm_bf16x3<<<grid, 256, SMEM_TOTAL>>>(cur_h, cur_l, Wc_hi, Wc_lo,
                                               bcomb, nxt_h, nxt_l, m, 512, 1024);
        __nv_bfloat16* t;
        t = cur_h; cur_h = nxt_h; nxt_h = t;
        t = cur_l; cur_l = nxt_l; nxt_l = t;
        rows = m;
    }

    proj_kernel<<<1, 64>>>(cur_h, cur_l, Wproj, bproj, out);
}

// round 7
// speedup vs baseline: 1.2777x; 1.2777x over previous
#include <cuda_runtime.h>
#include <cuda_bf16.h>
#include <cstdint>

// Tree-RNN, bf16x3-split GEMMs on mma.sync tensor cores.
// - Leaf: 128x128 tile kernel (warp tile 32x64), 3-stage cp.async ring.
// - Mid combines (m>=1024): 128x64 tile kernel, 4-stage ring.
// - Small combines (m<=512): split-K(4) 32x64 kernel + finalize.

// ---------------- device scratch (no allocation allowed) ----------------
__device__ __nv_bfloat16 g_leaf_hi[8192ull * 4096];
__device__ __nv_bfloat16 g_leaf_lo[8192ull * 4096];
__device__ __nv_bfloat16 g_We_hi[512 * 4096];
__device__ __nv_bfloat16 g_We_lo[512 * 4096];
__device__ __nv_bfloat16 g_Wc_hi[512 * 1024];
__device__ __nv_bfloat16 g_Wc_lo[512 * 1024];
__device__ __nv_bfloat16 g_hA[8192 * 512], g_lA[8192 * 512];
__device__ __nv_bfloat16 g_hB[4096 * 512], g_lB[4096 * 512];
#define KSPLIT 4
__device__ float g_part[KSPLIT * 512 * 512];   // split-K partials (4 MB)

// ---------------- PTX helpers ----------------
__device__ __forceinline__ void mma_bf16(float c[4], const uint32_t a[4],
                                         const uint32_t b0, const uint32_t b1) {
    asm volatile(
        "mma.sync.aligned.m16n8k16.row.col.f32.bf16.bf16.f32 "
        "{%0,%1,%2,%3}, {%4,%5,%6,%7}, {%8,%9}, {%0,%1,%2,%3};\n"
        : "+f"(c[0]), "+f"(c[1]), "+f"(c[2]), "+f"(c[3])
        : "r"(a[0]), "r"(a[1]), "r"(a[2]), "r"(a[3]), "r"(b0), "r"(b1));
}
__device__ __forceinline__ void cp16(uint32_t dst, const void* src, bool p) {
    asm volatile("cp.async.cg.shared.global [%0], [%1], 16, %2;"
                 :: "r"(dst), "l"(src), "r"(p ? 16 : 0));
}
__device__ __forceinline__ void cp_commit() {
    asm volatile("cp.async.commit_group;");
}
template <int N> __device__ __forceinline__ void cp_wait() {
    asm volatile("cp.async.wait_group %0;" :: "n"(N));
}
__device__ __forceinline__ void ldsm4(uint32_t r[4], uint32_t a) {
    asm volatile("ldmatrix.sync.aligned.m8n8.x4.shared.b16 {%0,%1,%2,%3}, [%4];"
                 : "=r"(r[0]), "=r"(r[1]), "=r"(r[2]), "=r"(r[3]) : "r"(a));
}
__device__ __forceinline__ uint32_t pack_bf2(__nv_bfloat16 a, __nv_bfloat16 b) {
    __nv_bfloat162 t{a, b};
    return *reinterpret_cast<uint32_t*>(&t);
}

// ---------------- fp32 -> bf16 hi/lo split (streaming) ----------------
__global__ void split_kernel(const float4* __restrict__ src,
                             uint2* __restrict__ hi, uint2* __restrict__ lo,
                             int n4)
{
    int i = blockIdx.x * blockDim.x + threadIdx.x;
    const int stride = gridDim.x * blockDim.x;
    for (; i < n4; i += stride) {
        float4 v = src[i];
        __nv_bfloat16 h0 = __float2bfloat16(v.x), h1 = __float2bfloat16(v.y);
        __nv_bfloat16 h2 = __float2bfloat16(v.z), h3 = __float2bfloat16(v.w);
        uint2 H, L;
        H.x = pack_bf2(h0, h1);
        H.y = pack_bf2(h2, h3);
        L.x = pack_bf2(__float2bfloat16(v.x - __bfloat162float(h0)),
                       __float2bfloat16(v.y - __bfloat162float(h1)));
        L.y = pack_bf2(__float2bfloat16(v.z - __bfloat162float(h2)),
                       __float2bfloat16(v.w - __bfloat162float(h3)));
        hi[i] = H;
        lo[i] = L;
    }
}

// ============================================================================
// Kernel 1: 128x128 tile (leaf). 8 warps (4M x 2N), warp tile 32x64.
// 3-stage ring (32 KB/stage), prefetch distance 2.
// ============================================================================
#define A_T2 16384
#define STAGE2 32768
#define SMEM2 (3 * STAGE2)     // 98304

__global__ __launch_bounds__(256, 2)
void gemm128(const __nv_bfloat16* __restrict__ Ahi,
             const __nv_bfloat16* __restrict__ Alo,
             const __nv_bfloat16* __restrict__ Whi,
             const __nv_bfloat16* __restrict__ Wlo,
             const float* __restrict__ bias,
             __nv_bfloat16* __restrict__ Chi,
             __nv_bfloat16* __restrict__ Clo,
             int M, int N, int K)
{
    extern __shared__ __align__(1024) char smem[];
    const uint32_t sbase = (uint32_t)__cvta_generic_to_shared(smem);

    const int tid  = threadIdx.x;
    const int lane = tid & 31;
    const int wid  = tid >> 5;
    const int wm   = (wid & 3) * 32;
    const int wn   = (wid >> 2) * 64;
    const int bm   = blockIdx.y * 128;
    const int bn   = blockIdx.x * 128;

    const int lr8   = lane & 7;
    const int g     = lane >> 3;
    const int mrow  = (g & 1) * 8;
    const int kcolB = (g >> 1) * 16;

    uint32_t aRow[2], aXm[2], bRow[4], bXm[4];
    #pragma unroll
    for (int mi = 0; mi < 2; mi++) {
        const uint32_t rB = (uint32_t)(wm + mi * 16 + mrow + lr8) * 128;
        aRow[mi] = rB;
        aXm[mi]  = (rB >> 3) & 0x70;
    }
    #pragma unroll
    for (int p = 0; p < 4; p++) {
        const uint32_t rB = (uint32_t)(wn + p * 16 + mrow + lr8) * 128;
        bRow[p] = A_T2 + rB;
        bXm[p]  = (rB >> 3) & 0x70;
    }

    float acc[2][8][4];
    #pragma unroll
    for (int i = 0; i < 2; i++)
        #pragma unroll
        for (int j = 0; j < 8; j++)
            #pragma unroll
            for (int v = 0; v < 4; v++) acc[i][j][v] = 0.f;

    const int nT = K / 32;

    auto stage = [&](int lt) {
        const uint32_t sb = sbase + (uint32_t)(lt % 3) * STAGE2;
        const int k0 = lt * 32;
        #pragma unroll
        for (int i = 0; i < 4; i++) {                 // A: 128 rows
            const int lin = tid + i * 256;
            const int r = lin >> 3;
            const int c = lin & 7;
            const uint32_t off = (uint32_t)r * 128 + (uint32_t)c * 16;
            const uint32_t sw = off ^ ((off >> 3) & 0x70);
            const bool pa = (bm + r) < M;
            const __nv_bfloat16* src = (c < 4) ? Ahi : Alo;
            cp16(sb + sw, src + (size_t)(bm + r) * K + k0 + (c & 3) * 8, pa);
        }
        #pragma unroll
        for (int i = 0; i < 4; i++) {                 // B: 128 rows
            const int lin = tid + i * 256;
            const int r = lin >> 3;
            const int c = lin & 7;
            const uint32_t off = (uint32_t)r * 128 + (uint32_t)c * 16;
            const uint32_t sw = off ^ ((off >> 3) & 0x70);
            const __nv_bfloat16* src = (c < 4) ? Whi : Wlo;
            cp16(sb + A_T2 + sw, src + (size_t)(bn + r) * K + k0 + (c & 3) * 8, true);
        }
        cp_commit();
    };

    stage(0);
    stage(1);

    for (int kt = 0; kt < nT; kt++) {
        if (kt + 1 < nT) cp_wait<1>();
        else             cp_wait<0>();
        __syncthreads();
        if (kt + 2 < nT) stage(kt + 2);

        const uint32_t s0 = sbase + (uint32_t)(kt % 3) * STAGE2;

        #pragma unroll
        for (int ks = 0; ks < 32; ks += 16) {
            const uint32_t colH = (uint32_t)(ks * 2) + kcolB;
            const uint32_t colL = 64u + (uint32_t)(ks * 2) + kcolB;
            uint32_t ah[2][4], al[2][4];
            #pragma unroll
            for (int mi = 0; mi < 2; mi++) {
                ldsm4(ah[mi], s0 + aRow[mi] + (colH ^ aXm[mi]));
                ldsm4(al[mi], s0 + aRow[mi] + (colL ^ aXm[mi]));
            }
            #pragma unroll
            for (int p = 0; p < 4; p++) {
                uint32_t bh[4], bl[4];
                ldsm4(bh, s0 + bRow[p] + (colH ^ bXm[p]));
                ldsm4(bl, s0 + bRow[p] + (colL ^ bXm[p]));
                #pragma unroll
                for (int mi = 0; mi < 2; mi++) {
                    mma_bf16(acc[mi][2 * p],     ah[mi], bh[0], bh[2]);
                    mma_bf16(acc[mi][2 * p + 1], ah[mi], bh[1], bh[3]);
                    mma_bf16(acc[mi][2 * p],     ah[mi], bl[0], bl[2]);
                    mma_bf16(acc[mi][2 * p + 1], ah[mi], bl[1], bl[3]);
                    mma_bf16(acc[mi][2 * p],     al[mi], bh[0], bh[2]);
                    mma_bf16(acc[mi][2 * p + 1], al[mi], bh[1], bh[3]);
                }
            }
        }
    }

    const int lq = (lane & 3) * 2;
    const int lr = lane >> 2;
    #pragma unroll
    for (int mi = 0; mi < 2; mi++) {
        #pragma unroll
        for (int ni = 0; ni < 8; ni++) {
            const int m0 = bm + wm + mi * 16 + lr;
            const int n  = bn + wn + ni * 8 + lq;
            const float bv0 = __ldg(bias + n), bv1 = __ldg(bias + n + 1);
            #pragma unroll
            for (int h = 0; h < 2; h++) {
                const int m = m0 + h * 8;
                if (m < M) {
                    float x0 = fmaxf(acc[mi][ni][2 * h]     + bv0, 0.f);
                    float x1 = fmaxf(acc[mi][ni][2 * h + 1] + bv1, 0.f);
                    __nv_bfloat16 h0 = __float2bfloat16(x0);
                    __nv_bfloat16 h1 = __float2bfloat16(x1);
                    __nv_bfloat16 l0 = __float2bfloat16(x0 - __bfloat162float(h0));
                    __nv_bfloat16 l1 = __float2bfloat16(x1 - __bfloat162float(h1));
                    *reinterpret_cast<uint32_t*>(Chi + (size_t)m * N + n) = pack_bf2(h0, h1);
                    *reinterpret_cast<uint32_t*>(Clo + (size_t)m * N + n) = pack_bf2(l0, l1);
                }
            }
        }
    }
}

// ============================================================================
// Kernel 2: 128x64 tile (mid combines), R5-proven version.
// ============================================================================
#define A_T1 16384
#define B_T1 8192
#define STAGE1 24576
#define SMEM1 (4 * STAGE1)    // 98304

__global__ __launch_bounds__(256, 2)
void gemm64(const __nv_bfloat16* __restrict__ Ahi,
            const __nv_bfloat16* __restrict__ Alo,
            const __nv_bfloat16* __restrict__ Whi,
            const __nv_bfloat16* __restrict__ Wlo,
            const float* __restrict__ bias,
            __nv_bfloat16* __restrict__ Chi,
            __nv_bfloat16* __restrict__ Clo,
            int M, int N, int K)
{
    extern __shared__ __align__(1024) char smem[];
    const uint32_t sbase = (uint32_t)__cvta_generic_to_shared(smem);

    const int tid  = threadIdx.x;
    const int lane = tid & 31;
    const int wid  = tid >> 5;
    const int wm   = (wid & 3) * 32;
    const int wn   = (wid >> 2) * 32;
    const int bm   = blockIdx.y * 128;
    const int bn   = blockIdx.x * 64;

    const int lr8   = lane & 7;
    const int g     = lane >> 3;
    const int mrow  = (g & 1) * 8;
    const int kcolB = (g >> 1) * 16;

    uint32_t aRow[2], aXm[2], bRow[2], bXm[2];
    #pragma unroll
    for (int mi = 0; mi < 2; mi++) {
        const uint32_t rB = (uint32_t)(wm + mi * 16 + mrow + lr8) * 128;
        aRow[mi] = rB;
        aXm[mi]  = (rB >> 3) & 0x70;
    }
    #pragma unroll
    for (int p = 0; p < 2; p++) {
        const uint32_t rB = (uint32_t)(wn + p * 16 + mrow + lr8) * 128;
        bRow[p] = A_T1 + rB;
        bXm[p]  = (rB >> 3) & 0x70;
    }

    float acc[2][4][4];
    #pragma unroll
    for (int i = 0; i < 2; i++)
        #pragma unroll
        for (int j = 0; j < 4; j++)
            #pragma unroll
            for (int v = 0; v < 4; v++) acc[i][j][v] = 0.f;

    const int nT = K / 32;

    auto stage = [&](int lt) {
        const uint32_t sb = sbase + (uint32_t)(lt & 3) * STAGE1;
        const int k0 = lt * 32;
        #pragma unroll
        for (int i = 0; i < 4; i++) {
            const int lin = tid + i * 256;
            const int r = lin >> 3;
            const int c = lin & 7;
            const uint32_t off = (uint32_t)r * 128 + (uint32_t)c * 16;
            const uint32_t sw = off ^ ((off >> 3) & 0x70);
            const bool pa = (bm + r) < M;
            const __nv_bfloat16* src = (c < 4) ? Ahi : Alo;
            cp16(sb + sw, src + (size_t)(bm + r) * K + k0 + (c & 3) * 8, pa);
        }
        #pragma unroll
        for (int i = 0; i < 2; i++) {
            const int lin = tid + i * 256;
            const int r = lin >> 3;
            const int c = lin & 7;
            const uint32_t off = (uint32_t)r * 128 + (uint32_t)c * 16;
            const uint32_t sw = off ^ ((off >> 3) & 0x70);
            const __nv_bfloat16* src = (c < 4) ? Whi : Wlo;
            cp16(sb + A_T1 + sw, src + (size_t)(bn + r) * K + k0 + (c & 3) * 8, true);
        }
        cp_commit();
    };

    stage(0);
    stage(1);
    stage(2);

    for (int kt = 0; kt < nT; kt++) {
        if (kt + 2 <= nT - 1)      cp_wait<2>();
        else if (kt + 1 <= nT - 1) cp_wait<1>();
        else                       cp_wait<0>();
        __syncthreads();
        if (kt + 3 < nT) stage(kt + 3);

        const uint32_t s0 = sbase + (uint32_t)(kt & 3) * STAGE1;

        #pragma unroll
        for (int ks = 0; ks < 32; ks += 16) {
            const uint32_t colH = (uint32_t)(ks * 2) + kcolB;
            const uint32_t colL = 64u + (uint32_t)(ks * 2) + kcolB;
            uint32_t ah[2][4], al[2][4], bh[2][4], bl[2][4];
            #pragma unroll
            for (int mi = 0; mi < 2; mi++) {
                ldsm4(ah[mi], s0 + aRow[mi] + (colH ^ aXm[mi]));
                ldsm4(al[mi], s0 + aRow[mi] + (colL ^ aXm[mi]));
            }
            #pragma unroll
            for (int p = 0; p < 2; p++) {
                ldsm4(bh[p], s0 + bRow[p] + (colH ^ bXm[p]));
                ldsm4(bl[p], s0 + bRow[p] + (colL ^ bXm[p]));
            }
            #pragma unroll
            for (int mi = 0; mi < 2; mi++)
                #pragma unroll
                for (int ni = 0; ni < 4; ni++) {
                    const int p = ni >> 1, q = ni & 1;
                    mma_bf16(acc[mi][ni], ah[mi], bh[p][q], bh[p][q + 2]);
                    mma_bf16(acc[mi][ni], ah[mi], bl[p][q], bl[p][q + 2]);
                    mma_bf16(acc[mi][ni], al[mi], bh[p][q], bh[p][q + 2]);
                }
        }
    }

    const int lq = (lane & 3) * 2;
    const int lr = lane >> 2;
    #pragma unroll
    for (int mi = 0; mi < 2; mi++) {
        #pragma unroll
        for (int ni = 0; ni < 4; ni++) {
            const int m0 = bm + wm + mi * 16 + lr;
            const int n  = bn + wn + ni * 8 + lq;
            const float bv0 = __ldg(bias + n), bv1 = __ldg(bias + n + 1);
            #pragma unroll
            for (int h = 0; h < 2; h++) {
                const int m = m0 + h * 8;
                if (m < M) {
                    float x0 = fmaxf(acc[mi][ni][2 * h]     + bv0, 0.f);
                    float x1 = fmaxf(acc[mi][ni][2 * h + 1] + bv1, 0.f);
                    __nv_bfloat16 h0 = __float2bfloat16(x0);
                    __nv_bfloat16 h1 = __float2bfloat16(x1);
                    __nv_bfloat16 l0 = __float2bfloat16(x0 - __bfloat162float(h0));
                    __nv_bfloat16 l1 = __float2bfloat16(x1 - __bfloat162float(h1));
                    *reinterpret_cast<uint32_t*>(Chi + (size_t)m * N + n) = pack_bf2(h0, h1);
                    *reinterpret_cast<uint32_t*>(Clo + (size_t)m * N + n) = pack_bf2(l0, l1);
                }
            }
        }
    }
}

// ============================================================================
// Kernel 3: small-M split-K GEMM. 32x64 tile, 128 threads (4 warps, 2Mx2N),
// grid (N/64, ceil(M/32), KSPLIT). Writes fp32 partials (no bias/act).
// ============================================================================
#define A_T3 4096
#define STAGE3 12288
#define SMEM3 (3 * STAGE3)    // 36864

__global__ __launch_bounds__(128, 4)
void gemm_small(const __nv_bfloat16* __restrict__ Ahi,
                const __nv_bfloat16* __restrict__ Alo,
                const __nv_bfloat16* __restrict__ Whi,
                const __nv_bfloat16* __restrict__ Wlo,
                float* __restrict__ part,
                int M, int N, int K)
{
    extern __shared__ __align__(1024) char smem[];
    const uint32_t sbase = (uint32_t)__cvta_generic_to_shared(smem);

    const int tid  = threadIdx.x;
    const int lane = tid & 31;
    const int wid  = tid >> 5;
    const int wm   = (wid & 1) * 16;
    const int wn   = (wid >> 1) * 32;
    const int bm   = blockIdx.y * 32;
    const int bn   = blockIdx.x * 64;
    const int kbase = blockIdx.z * (K / KSPLIT);

    const int lr8   = lane & 7;
    const int g     = lane >> 3;
    const int mrow  = (g & 1) * 8;
    const int kcolB = (g >> 1) * 16;

    uint32_t aRowB, aXm, bRow[2], bXm[2];
    {
        const uint32_t rB = (uint32_t)(wm + mrow + lr8) * 128;
        aRowB = rB;
        aXm   = (rB >> 3) & 0x70;
    }
    #pragma unroll
    for (int p = 0; p < 2; p++) {
        const uint32_t rB = (uint32_t)(wn + p * 16 + mrow + lr8) * 128;
        bRow[p] = A_T3 + rB;
        bXm[p]  = (rB >> 3) & 0x70;
    }

    float acc[4][4];
    #pragma unroll
    for (int j = 0; j < 4; j++)
        #pragma unroll
        for (int v = 0; v < 4; v++) acc[j][v] = 0.f;

    const int nT = (K / KSPLIT) / 32;     // 8 for K=1024

    auto stage = [&](int lt) {
        const uint32_t sb = sbase + (uint32_t)(lt % 3) * STAGE3;
        const int k0 = kbase + lt * 32;
        #pragma unroll
        for (int i = 0; i < 2; i++) {                 // A: 32 rows
            const int lin = tid + i * 128;
            const int r = lin >> 3;
            const int c = lin & 7;
            const uint32_t off = (uint32_t)r * 128 + (uint32_t)c * 16;
            const uint32_t sw = off ^ ((off >> 3) & 0x70);
            const bool pa = (bm + r) < M;
            const __nv_bfloat16* src = (c < 4) ? Ahi : Alo;
            cp16(sb + sw, src + (size_t)(bm + r) * K + k0 + (c & 3) * 8, pa);
        }
        #pragma unroll
        for (int i = 0; i < 4; i++) {                 // B: 64 rows
            const int lin = tid + i * 128;
            const int r = lin >> 3;
            const int c = lin & 7;
            const uint32_t off = (uint32_t)r * 128 + (uint32_t)c * 16;
            const uint32_t sw = off ^ ((off >> 3) & 0x70);
            const __nv_bfloat16* src = (c < 4) ? Whi : Wlo;
            cp16(sb + A_T3 + sw, src + (size_t)(bn + r) * K + k0 + (c & 3) * 8, true);
        }
        cp_commit();
    };

    stage(0);
    stage(1);

    for (int kt = 0; kt < nT; kt++) {
        if (kt + 1 < nT) cp_wait<1>();
        else             cp_wait<0>();
        __syncthreads();
        if (kt + 2 < nT) stage(kt + 2);

        const uint32_t s0 = sbase + (uint32_t)(kt % 3) * STAGE3;

        #pragma unroll
        for (int ks = 0; ks < 32; ks += 16) {
            const uint32_t colH = (uint32_t)(ks * 2) + kcolB;
            const uint32_t colL = 64u + (uint32_t)(ks * 2) + kcolB;
            uint32_t ah[4], al[4], bh[2][4], bl[2][4];
            ldsm4(ah, s0 + aRowB + (colH ^ aXm));
            ldsm4(al, s0 + aRowB + (colL ^ aXm));
            #pragma unroll
            for (int p = 0; p < 2; p++) {
                ldsm4(bh[p], s0 + bRow[p] + (colH ^ bXm[p]));
                ldsm4(bl[p], s0 + bRow[p] + (colL ^ bXm[p]));
            }
            #pragma unroll
            for (int ni = 0; ni < 4; ni++) {
                const int p = ni >> 1, q = ni & 1;
                mma_bf16(acc[ni], ah, bh[p][q], bh[p][q + 2]);
                mma_bf16(acc[ni], ah, bl[p][q], bl[p][q + 2]);
                mma_bf16(acc[ni], al, bh[p][q], bh[p][q + 2]);
            }
        }
    }

    // write fp32 partials: part[((bz*M)+m)*N + n]
    const int lq = (lane & 3) * 2;
    const int lr = lane >> 2;
    #pragma unroll
    for (int ni = 0; ni < 4; ni++) {
        const int m0 = bm + wm + lr;
        const int n  = bn + wn + ni * 8 + lq;
        #pragma unroll
        for (int h = 0; h < 2; h++) {
            const int m = m0 + h * 8;
            if (m < M) {
                float* dst = part + ((size_t)blockIdx.z * M + m) * N + n;
                dst[0] = acc[ni][2 * h];
                dst[1] = acc[ni][2 * h + 1];
            }
        }
    }
}

// finalize: sum KSPLIT partials + bias + relu + hi/lo split
__global__ void finalize_small(const float* __restrict__ part,
                               const float* __restrict__ bias,
                               __nv_bfloat16* __restrict__ Chi,
                               __nv_bfloat16* __restrict__ Clo,
                               int M, int N)
{
    const int total2 = M * N / 2;
    int i = blockIdx.x * blockDim.x + threadIdx.x;
    const int stride = gridDim.x * blockDim.x;
    for (; i < total2; i += stride) {
        const int m = (2 * i) / N;
        const int n = (2 * i) % N;
        float s0 = 0.f, s1 = 0.f;
        #pragma unroll
        for (int z = 0; z < KSPLIT; z++) {
            const float* p = part + ((size_t)z * M + m) * N + n;
            s0 += p[0];
            s1 += p[1];
        }
        float x0 = fmaxf(s0 + bias[n], 0.f);
        float x1 = fmaxf(s1 + bias[n + 1], 0.f);
        __nv_bfloat16 h0 = __float2bfloat16(x0);
        __nv_bfloat16 h1 = __float2bfloat16(x1);
        __nv_bfloat16 l0 = __float2bfloat16(x0 - __bfloat162float(h0));
        __nv_bfloat16 l1 = __float2bfloat16(x1 - __bfloat162float(h1));
        *reinterpret_cast<uint32_t*>(Chi + (size_t)m * N + n) = pack_bf2(h0, h1);
        *reinterpret_cast<uint32_t*>(Clo + (size_t)m * N + n) = pack_bf2(l0, l1);
    }
}

// Root projection
__global__ void proj_kernel(const __nv_bfloat16* __restrict__ hhi,
                            const __nv_bfloat16* __restrict__ hlo,
                            const float* __restrict__ Wp,
                            const float* __restrict__ bp,
                            float* __restrict__ out)
{
    const int w    = threadIdx.x >> 5;
    const int lane = threadIdx.x & 31;
    float s = 0.f;
    for (int k = lane; k < 512; k += 32) {
        const float hv = __bfloat162float(hhi[k]) + __bfloat162float(hlo[k]);
        s = fmaf(hv, Wp[w * 512 + k], s);
    }
    #pragma unroll
    for (int o = 16; o > 0; o >>= 1)
        s += __shfl_xor_sync(0xffffffffu, s, o);
    if (lane == 0) out[w] = s + bp[w];
}

extern "C" void kernel_launch(void* const* d_in, const int* in_sizes, int n_in,
                              void* d_out, int out_size)
{
    const float* leaf  = (const float*)d_in[0];
    const float* Wemb  = (const float*)d_in[1];
    const float* bemb  = (const float*)d_in[2];
    const float* Wcomb = (const float*)d_in[3];
    const float* bcomb = (const float*)d_in[4];
    const float* Wproj = (const float*)d_in[5];
    const float* bproj = (const float*)d_in[6];
    float* out = (float*)d_out;

    __nv_bfloat16 *leaf_hi, *leaf_lo, *We_hi, *We_lo, *Wc_hi, *Wc_lo;
    __nv_bfloat16 *hA, *lA, *hB, *lB;
    float* part;
    cudaGetSymbolAddress((void**)&leaf_hi, g_leaf_hi);
    cudaGetSymbolAddress((void**)&leaf_lo, g_leaf_lo);
    cudaGetSymbolAddress((void**)&We_hi, g_We_hi);
    cudaGetSymbolAddress((void**)&We_lo, g_We_lo);
    cudaGetSymbolAddress((void**)&Wc_hi, g_Wc_hi);
    cudaGetSymbolAddress((void**)&Wc_lo, g_Wc_lo);
    cudaGetSymbolAddress((void**)&hA, g_hA);
    cudaGetSymbolAddress((void**)&lA, g_lA);
    cudaGetSymbolAddress((void**)&hB, g_hB);
    cudaGetSymbolAddress((void**)&lB, g_lB);
    cudaGetSymbolAddress((void**)&part, g_part);

    cudaFuncSetAttribute(gemm128,
                         cudaFuncAttributeMaxDynamicSharedMemorySize, SMEM2);
    cudaFuncSetAttribute(gemm64,
                         cudaFuncAttributeMaxDynamicSharedMemorySize, SMEM1);
    cudaFuncSetAttribute(gemm_small,
                         cudaFuncAttributeMaxDynamicSharedMemorySize, SMEM3);

    // ---- pre-split fp32 inputs into bf16 hi/lo ----
    split_kernel<<<4096, 256>>>((const float4*)leaf,
                                (uint2*)leaf_hi, (uint2*)leaf_lo, 8192 * 4096 / 4);
    split_kernel<<<1024, 256>>>((const float4*)Wemb,
                                (uint2*)We_hi, (uint2*)We_lo, 512 * 4096 / 4);
    split_kernel<<<512, 256>>>((const float4*)Wcomb,
                               (uint2*)Wc_hi, (uint2*)Wc_lo, 512 * 1024 / 4);

    // ---- leaf embedding: [8192,4096] @ [512,4096]^T -> hA/lA ----
    {
        dim3 grid(512 / 128, 8192 / 128);
        gemm128<<<grid, 256, SMEM2>>>(leaf_hi, leaf_lo, We_hi, We_lo,
                                      bemb, hA, lA, 8192, 512, 4096);
    }

    // ---- 13 combine levels: [rows,512] viewed as [rows/2,1024] ----
    __nv_bfloat16 *cur_h = hA, *cur_l = lA, *nxt_h = hB, *nxt_l = lB;
    int rows = 8192;
    while (rows > 1) {
        const int m = rows / 2;
        if (m >= 1024) {
            dim3 grid(512 / 64, (m + 127) / 128);
            gemm64<<<grid, 256, SMEM1>>>(cur_h, cur_l, Wc_hi, Wc_lo,
                                         bcomb, nxt_h, nxt_l, m, 512, 1024);
        } else {
            dim3 grid(512 / 64, (m + 31) / 32, KSPLIT);
            gemm_small<<<grid, 128, SMEM3>>>(cur_h, cur_l, Wc_hi, Wc_lo,
                                             part, m, 512, 1024);
            const int total2 = m * 512 / 2;
            const int blocks = (total2 + 255) / 256;
            finalize_small<<<blocks, 256>>>(part, bcomb, nxt_h, nxt_l, m, 512);
        }
        __nv_bfloat16* t;
        t = cur_h; cur_h = nxt_h; nxt_h = t;
        t = cur_l; cur_l = nxt_l; nxt_l = t;
        rows = m;
    }

    proj_kernel<<<1, 64>>>(cur_h, cur_l, Wproj, bproj, out);
}